// round 12
// baseline (speedup 1.0000x reference)
#include <cuda_runtime.h>
#include <cstdint>

// Problem constants (fixed shapes for this problem)
#define T_LEN 4096
#define B_LEN 4096
#define NTILES (T_LEN / 32)

// LUT: log2-spaced midpoint-value table of
//   g(s) = (1/sqrt(2pi)) * int_{-5}^{5} (1 - tanh(sqrt(s)*z)^2) exp(-z^2/2) dz
// word index = float_bits(s) >> 15. 256 bins/octave, s in [2^-14, 2^8).
#define OCTAVES 22
#define NLUT (OCTAVES * 256)      // 5632 entries, f32
#define BASE_BITS 0x38800000u     // float bits of 2^-14
#define BASE_IDX  (BASE_BITS >> 15)   // 28928
#define EPS_S 6.103515625e-05f    // 2^-14, added to u^2 so s >= 2^-14 always

__device__ float g_lut[NLUT];

// ---------------------------------------------------------------------------
// Build kernel: block j computes g at the BIT-midpoint of bin j via composite
// Simpson on [0,5] (even integrand -> x2), f32 evals, double accumulation.
// Adaptive n: integrand width ~1/delta; only large-delta bins need n=512.
// ---------------------------------------------------------------------------
__global__ void build_lut_kernel() {
    int j = blockIdx.x;            // 0 .. NLUT-1
    int lane = threadIdx.x;        // 32
    unsigned bits = BASE_BITS + ((unsigned)j << 15) + (1u << 14);  // bin midpoint
    float delta = sqrtf(__uint_as_float(bits));

    int n = (delta > 4.0f) ? 512 : 128;
    float h = 5.0f / (float)n;
    double acc = 0.0;
    for (int i = lane; i <= n; i += 32) {
        float z = h * (float)i;
        float t = tanhf(delta * z);
        float f = (1.0f - t * t) * expf(-0.5f * z * z);
        float coef = (i == 0 || i == n) ? 1.0f : ((i & 1) ? 4.0f : 2.0f);
        acc += (double)(f * coef);
    }
    #pragma unroll
    for (int o = 16; o; o >>= 1)
        acc += __shfl_down_sync(0xffffffffu, acc, o);
    if (lane == 0)
        g_lut[j] = (float)(acc * ((double)h / 3.0) * 2.0 * 0.3989422804014327);
}

// ---------------------------------------------------------------------------
// Warp-specialized scan. Block = 64 threads.
//   warp 0: k-chain only. Pairs fed through an explicit 4-deep register ring
//           (8 regs -> allocator keeps it; load distance ~4 steps >> LDS lat).
//           Step chain: s=FFMA(k,k,uu) -> SHF -> LDS.32(lut) -> FFMA(k).
//   warp 1: direct __ldg of u (one 128B line/lane/tile, register
//           double-buffered); v/W recurrence ONE TILE AHEAD writing
//           (uu, r)=(u^2+eps, 0.104*W) pairs; z drain (applies 2.1x).
// One __syncthreads() per 32-step tile.
// ---------------------------------------------------------------------------
__global__ __launch_bounds__(64, 1)
void scan_kernel(const float* __restrict__ u, float* __restrict__ out) {
    __shared__ float  lut_s[NLUT];         // 22528 B
    __shared__ float2 pair_s[2][32 * 33];  // 16896 B [row*33 + time] = (uu, r)
    __shared__ float  z_s[2][32 * 33];     // 8448 B  [row*33 + time], raw k

    int tid  = threadIdx.x;
    int lane = tid & 31;
    int wid  = tid >> 5;
    int b0 = blockIdx.x * 32;

    // Cooperative LUT stage (both warps, float4 copies)
    {
        const float4* src = (const float4*)g_lut;     // NLUT/4 = 1408
        float4* dst = (float4*)lut_s;
        for (int i = tid; i < NLUT / 4; i += 64) dst[i] = src[i];
    }

    // Pre-offset LUT pointer: g = lutp[bits(s) >> 15]; index stays in
    // [BASE_IDX, BASE_IDX + NLUT) because EPS_S <= s < 256 always.
    const float* __restrict__ lutp = (const float*)lut_s - BASE_IDX;

    float W = 0.0f;  // I/O warp's v-state: v = 0.2*W, W <- 0.8*W + u
    const float4* __restrict__ urow =
        (const float4*)(u + (size_t)(b0 + lane) * T_LEN);
    float4 ubuf[8];

    if (wid == 1) {
        // Load u tile 0, build pairs for tile 0, then preload u tile 1.
        #pragma unroll
        for (int j = 0; j < 8; ++j) ubuf[j] = __ldg(urow + j);
        float2* pp = &pair_s[0][lane * 33];
        #pragma unroll
        for (int j = 0; j < 8; ++j) {
            float uv[4] = {ubuf[j].x, ubuf[j].y, ubuf[j].z, ubuf[j].w};
            #pragma unroll
            for (int q4 = 0; q4 < 4; ++q4) {
                float uin = uv[q4];
                W = fmaf(0.8f, W, uin);
                pp[j * 4 + q4] = make_float2(fmaf(uin, uin, EPS_S), 0.104f * W);
            }
        }
        #pragma unroll
        for (int j = 0; j < 8; ++j) ubuf[j] = __ldg(urow + 8 + j);
    } else {
        out[(size_t)(b0 + lane) * (T_LEN + 1)] = 0.0f;  // z_hist[:,0] = 0
    }
    __syncthreads();

    float k = 0.0f;

    #pragma unroll 1
    for (int t = 0; t < NTILES; ++t) {
        if (wid == 0) {
            // ---- compute warp: 32 chain steps, 4-deep pair ring ----
            const float2* __restrict__ pp = &pair_s[t & 1][lane * 33];
            float* __restrict__ zt = &z_s[t & 1][lane * 33];
            float2 ring[4];
            #pragma unroll
            for (int c = 0; c < 4; ++c) ring[c] = pp[c];

            #pragma unroll
            for (int c = 0; c < 32; ++c) {
                float2 pr = ring[c & 3];
                if (c + 4 < 32) ring[c & 3] = pp[c + 4];  // static -> regs
                float q  = fmaf(0.28f, k, pr.y);
                float kk = 0.8f * k;
                float s  = fmaf(k, k, pr.x);
                unsigned widx = __float_as_uint(s) >> 15;
                float g = lutp[widx];
                k = fmaf(g, q, kk);
                zt[c] = k;
            }
        } else {
            // ---- I/O warp ----
            if (t + 1 < NTILES) {
                // Build pairs for tile t+1 from register-buffered u
                float2* pp = &pair_s[(t + 1) & 1][lane * 33];
                #pragma unroll
                for (int j = 0; j < 8; ++j) {
                    float uv[4] = {ubuf[j].x, ubuf[j].y, ubuf[j].z, ubuf[j].w};
                    #pragma unroll
                    for (int q4 = 0; q4 < 4; ++q4) {
                        float uin = uv[q4];
                        W = fmaf(0.8f, W, uin);
                        pp[j * 4 + q4] =
                            make_float2(fmaf(uin, uin, EPS_S), 0.104f * W);
                    }
                }
                // Prefetch u for tile t+2 (plenty of latency slack)
                if (t + 2 < NTILES) {
                    #pragma unroll
                    for (int j = 0; j < 8; ++j)
                        ubuf[j] = __ldg(urow + (size_t)(t + 2) * 8 + j);
                }
            }
            if (t > 0) {
                // Drain z tile t-1: r = row, lane = time (coalesced per r)
                const float* zs = z_s[(t - 1) & 1];
                float* dst = out + (size_t)b0 * (T_LEN + 1) + 1
                           + (size_t)(t - 1) * 32 + lane;
                #pragma unroll
                for (int r = 0; r < 32; ++r)
                    dst[(size_t)r * (T_LEN + 1)] = 2.1f * zs[r * 33 + lane];
            }
        }
        __syncthreads();
    }

    if (wid == 1) {
        const float* zs = z_s[(NTILES - 1) & 1];
        float* dst = out + (size_t)b0 * (T_LEN + 1) + 1
                   + (size_t)(NTILES - 1) * 32 + lane;
        #pragma unroll
        for (int r = 0; r < 32; ++r)
            dst[(size_t)r * (T_LEN + 1)] = 2.1f * zs[r * 33 + lane];
    }
}

// ---------------------------------------------------------------------------
extern "C" void kernel_launch(void* const* d_in, const int* in_sizes, int n_in,
                              void* d_out, int out_size) {
    const float* u = (const float*)d_in[0];
    float* out = (float*)d_out;
    (void)in_sizes; (void)n_in; (void)out_size;

    build_lut_kernel<<<NLUT, 32>>>();
    scan_kernel<<<B_LEN / 32, 64>>>(u, out);
}